// round 4
// baseline (speedup 1.0000x reference)
#include <cuda_runtime.h>

#define IMG 256
#define NG 1024
#define PIX (1.0f/256.0f)
#define T_TH 1e-4f

// Sorted + packed per-Gaussian data (device scratch, no allocs)
// g_cull: mx, my, rad2, pad
// g_q:    c00', c01', c11', k'   (c' = -0.5*log2e*invCov, k' = log2(alpha))
// g_c:    cr, cg, cb, pad
__device__ float4 g_cull[NG];
__device__ float4 g_q[NG];
__device__ float4 g_c[NG];

// ---------------------------------------------------------------------------
// Kernel 1: parallel rank sort (8 blocks x 128 threads). Each thread computes
// the depth-rank of one Gaussian (stable: ties broken by index) and scatters
// its packed, precomputed record to the sorted position.
// ---------------------------------------------------------------------------
__global__ void __launch_bounds__(128) prep_kernel(const float* __restrict__ mean,
                                                   const float* __restrict__ cov,
                                                   const float* __restrict__ color,
                                                   const float* __restrict__ alpha,
                                                   const float* __restrict__ depth) {
    __shared__ float sd[NG];
    int tid = threadIdx.x;
    for (int i = tid; i < NG; i += 128) sd[i] = depth[i];
    __syncthreads();

    int i = blockIdx.x*128 + tid;
    float di = sd[i];
    int rank = 0;
    #pragma unroll 8
    for (int j = 0; j < NG; j++) {
        float dj = sd[j];
        rank += (dj < di) || (dj == di && j < i);
    }

    float a = cov[i*4+0], b = cov[i*4+1], c = cov[i*4+2], d = cov[i*4+3];
    float det = a*d - b*c;
    const float L2E = 1.4426950408889634f;
    float i00  = d / det;
    float i11  = a / det;
    float ioff = -(b + c) / det;
    float mx = mean[i*2+0], my = mean[i*2+1];
    // conservative radius^2: quad > 40 outside => contribution < alpha*e^-20
    float bs      = 0.5f*(b + c);
    float half_tr = 0.5f*(a + d);
    float disc    = sqrtf(0.25f*(a - d)*(a - d) + bs*bs);
    float al = alpha[i];
    g_cull[rank] = make_float4(mx, my, 40.0f*(half_tr + disc), 0.0f);
    g_q[rank]    = make_float4(-0.5f*L2E*i00, -0.5f*L2E*ioff, -0.5f*L2E*i11,
                               __log2f(fmaxf(al, 1e-30f)));
    g_c[rank]    = make_float4(color[i*3+0], color[i*3+1], color[i*3+2], 0.0f);
}

// ---------------------------------------------------------------------------
// Kernel 2: 128 threads per 16x8 pixel tile (512 blocks).
// Per sorted chunk of 128: per-warp cull+compact into warp-private regions
// (double-buffered), ONE barrier (__syncthreads_and early exit), then
// composite regions 0..3 in order (preserves global depth order).
// ---------------------------------------------------------------------------
__global__ void __launch_bounds__(128) render_kernel(const float* __restrict__ bg,
                                                     const float* __restrict__ topleft,
                                                     float* __restrict__ out) {
    __shared__ float4 sA[2][128];   // mx, my, c00', c01'
    __shared__ float4 sB[2][128];   // c11', k', cr, cg
    __shared__ float  sC[2][128];   // cb
    __shared__ int    sN[2][4];

    int tid  = threadIdx.x;
    int lane = tid & 31, warp = tid >> 5;

    float tlx = topleft[0], tly = topleft[1];
    float x0 = (blockIdx.x*16 + 0.5f)*PIX - tlx;
    float x1 = (blockIdx.x*16 + 15.5f)*PIX - tlx;
    float y0 = (blockIdx.y*8 + 0.5f)*PIX - tly;
    float y1 = (blockIdx.y*8 + 7.5f)*PIX - tly;

    int tx = tid & 15, ty = tid >> 4;
    float px = (blockIdx.x*16 + tx + 0.5f)*PIX - tlx;
    float py = (blockIdx.y*8 + ty + 0.5f)*PIX - tly;

    int pi = ((blockIdx.y*8 + ty)*IMG + blockIdx.x*16 + tx)*3;
    float bgr = bg[pi+0], bgg = bg[pi+1], bgb = bg[pi+2];

    float T = 1.0f, cr = 0.0f, cg = 0.0f, cb = 0.0f;

    #pragma unroll 1
    for (int chunk = 0; chunk < 8; chunk++) {
        int buf = chunk & 1;
        int g = chunk*128 + tid;
        float4 cu = g_cull[g];
        float cx = fminf(fmaxf(cu.x, x0), x1) - cu.x;
        float cy = fminf(fmaxf(cu.y, y0), y1) - cu.y;
        bool keep = (cx*cx + cy*cy) <= cu.z;
        unsigned bal = __ballot_sync(0xffffffffu, keep);
        if (keep) {
            int pos = warp*32 + __popc(bal & ((1u << lane) - 1u));
            float4 qv = g_q[g];
            float4 cv = g_c[g];
            sA[buf][pos] = make_float4(cu.x, cu.y, qv.x, qv.y);
            sB[buf][pos] = make_float4(qv.z, qv.w, cv.x, cv.y);
            sC[buf][pos] = cv.z;
        }
        if (lane == 0) sN[buf][warp] = __popc(bal);

        // Single barrier: publishes this chunk's regions, protects previous
        // chunk's buffer from reuse, and performs the block-wide early exit.
        if (__syncthreads_and(T <= T_TH)) break;

        if (T > T_TH) {
            #pragma unroll 1
            for (int w2 = 0; w2 < 4; w2++) {
                int base = w2*32;
                int n = sN[buf][w2];
                for (int i = 0; i < n; i += 4) {
                    float ax[4], rr[4], gg[4], bb[4];
                    #pragma unroll
                    for (int u = 0; u < 4; u++) {
                        int iu = i + u;
                        bool vld = iu < n;
                        int idx = base + (vld ? iu : 0);
                        float4 A = sA[buf][idx];
                        float4 B = sB[buf][idx];
                        float dx = px - A.x, dy = py - A.y;
                        float qd = dx*(A.z*dx + A.w*dy) + (B.x*dy*dy + B.y);
                        float av = fminf(exp2f(qd), 0.99f);
                        ax[u] = vld ? av : 0.0f;
                        rr[u] = B.z; gg[u] = B.w; bb[u] = sC[buf][idx];
                    }
                    float q0 = 1.0f-ax[0], q1 = 1.0f-ax[1], q2 = 1.0f-ax[2], q3 = 1.0f-ax[3];
                    float p2 = q0*q1;
                    float Tn = T * (p2*(q2*q3));
                    if (Tn > T_TH) {
                        // fast path: all four steps provably active (T monotone)
                        float t0 = T, t1 = T*q0, t2 = T*p2, t3 = t2*q2;
                        cr = fmaf(ax[0]*t0, rr[0], cr);
                        cg = fmaf(ax[0]*t0, gg[0], cg);
                        cb = fmaf(ax[0]*t0, bb[0], cb);
                        cr = fmaf(ax[1]*t1, rr[1], cr);
                        cg = fmaf(ax[1]*t1, gg[1], cg);
                        cb = fmaf(ax[1]*t1, bb[1], cb);
                        cr = fmaf(ax[2]*t2, rr[2], cr);
                        cg = fmaf(ax[2]*t2, gg[2], cg);
                        cb = fmaf(ax[2]*t2, bb[2], cb);
                        cr = fmaf(ax[3]*t3, rr[3], cr);
                        cg = fmaf(ax[3]*t3, gg[3], cg);
                        cb = fmaf(ax[3]*t3, bb[3], cb);
                        T = Tn;
                    } else {
                        // crossing group: exact masked sequential (runs once)
                        #pragma unroll
                        for (int u = 0; u < 4; u++) {
                            if (T > T_TH) {
                                float w = ax[u] * T;
                                cr = fmaf(w, rr[u], cr);
                                cg = fmaf(w, gg[u], cg);
                                cb = fmaf(w, bb[u], cb);
                                T *= (1.0f - ax[u]);
                            }
                        }
                    }
                    if (T <= T_TH) break;
                }
                if (T <= T_TH) break;
            }
        }
    }

    out[pi+0] = cr + T*bgr;
    out[pi+1] = cg + T*bgg;
    out[pi+2] = cb + T*bgb;
}

extern "C" void kernel_launch(void* const* d_in, const int* in_sizes, int n_in,
                              void* d_out, int out_size) {
    const float* mean    = (const float*)d_in[0];
    const float* cov     = (const float*)d_in[1];
    const float* color   = (const float*)d_in[2];
    const float* alpha   = (const float*)d_in[3];
    const float* depth   = (const float*)d_in[4];
    const float* bg      = (const float*)d_in[5];
    const float* topleft = (const float*)d_in[6];

    prep_kernel<<<8, 128>>>(mean, cov, color, alpha, depth);
    dim3 grid(IMG/16, IMG/8), block(128);
    render_kernel<<<grid, block>>>(bg, topleft, (float*)d_out);
}

// round 5
// speedup vs baseline: 1.1746x; 1.1746x over previous
#include <cuda_runtime.h>

#define IMG 256
#define NG 1024
#define PIX (1.0f/256.0f)
#define T_TH 1e-4f

// Sorted + packed per-Gaussian data (device scratch, no allocs)
// g_cull: mx, my, rad2, pad
// g_q:    c00', c01', c11', k'   (c' = -0.5*log2e*invCov, k' = log2(alpha))
// g_c:    cr, cg, cb, pad
__device__ float4 g_cull[NG];
__device__ float4 g_q[NG];
__device__ float4 g_c[NG];

// ---------------------------------------------------------------------------
// Kernel 1: parallel rank sort (8 blocks x 128 threads), float4-vectorized
// compare loop with 4 accumulators; scatter packed records to sorted slots.
// ---------------------------------------------------------------------------
__global__ void __launch_bounds__(128) prep_kernel(const float* __restrict__ mean,
                                                   const float* __restrict__ cov,
                                                   const float* __restrict__ color,
                                                   const float* __restrict__ alpha,
                                                   const float* __restrict__ depth) {
    __shared__ float4 sd4[NG/4];
    int tid = threadIdx.x;
    const float4* d4g = (const float4*)depth;
    for (int i = tid; i < NG/4; i += 128) sd4[i] = d4g[i];
    __syncthreads();

    int i = blockIdx.x*128 + tid;
    float di = ((const float*)sd4)[i];
    int r0 = 0, r1 = 0, r2 = 0, r3 = 0;
    #pragma unroll 4
    for (int j4 = 0; j4 < NG/4; j4++) {
        float4 d = sd4[j4];
        int j = j4*4;
        r0 += (d.x < di) || (d.x == di && (j+0) < i);
        r1 += (d.y < di) || (d.y == di && (j+1) < i);
        r2 += (d.z < di) || (d.z == di && (j+2) < i);
        r3 += (d.w < di) || (d.w == di && (j+3) < i);
    }
    int rank = (r0 + r1) + (r2 + r3);

    float a = cov[i*4+0], b = cov[i*4+1], c = cov[i*4+2], d = cov[i*4+3];
    float det = a*d - b*c;
    const float L2E = 1.4426950408889634f;
    float i00  = d / det;
    float i11  = a / det;
    float ioff = -(b + c) / det;
    float mx = mean[i*2+0], my = mean[i*2+1];
    // conservative radius^2: quad > 40 outside => contribution < alpha*e^-20
    float bs      = 0.5f*(b + c);
    float half_tr = 0.5f*(a + d);
    float disc    = sqrtf(0.25f*(a - d)*(a - d) + bs*bs);
    float al = alpha[i];
    g_cull[rank] = make_float4(mx, my, 40.0f*(half_tr + disc), 0.0f);
    g_q[rank]    = make_float4(-0.5f*L2E*i00, -0.5f*L2E*ioff, -0.5f*L2E*i11,
                               __log2f(fmaxf(al, 1e-30f)));
    g_c[rank]    = make_float4(color[i*3+0], color[i*3+1], color[i*3+2], 0.0f);
}

// ---------------------------------------------------------------------------
// Kernel 2: 256 threads per 16x16 pixel tile (256 blocks).
// Per sorted chunk of 256: block-wide cull+compact (double-buffered,
// 2 barriers/chunk, early-exit fused into the 2nd barrier), then composite
// the contiguous survivor list in depth order with groups of 4.
// ---------------------------------------------------------------------------
__global__ void __launch_bounds__(256) render_kernel(const float* __restrict__ bg,
                                                     const float* __restrict__ topleft,
                                                     float* __restrict__ out) {
    __shared__ float4 sA[2][256];   // mx, my, c00', c01'
    __shared__ float4 sB[2][256];   // c11', k', cr, cg
    __shared__ float  sC[2][256];   // cb
    __shared__ int    sW[2][8];     // per-warp survivor counts

    int tid  = threadIdx.x;
    int lane = tid & 31, warp = tid >> 5;

    float tlx = topleft[0], tly = topleft[1];
    float x0 = (blockIdx.x*16 + 0.5f)*PIX - tlx;
    float x1 = (blockIdx.x*16 + 15.5f)*PIX - tlx;
    float y0 = (blockIdx.y*16 + 0.5f)*PIX - tly;
    float y1 = (blockIdx.y*16 + 15.5f)*PIX - tly;

    int tx = tid & 15, ty = tid >> 4;
    float px = (blockIdx.x*16 + tx + 0.5f)*PIX - tlx;
    float py = (blockIdx.y*16 + ty + 0.5f)*PIX - tly;

    int pi = ((blockIdx.y*16 + ty)*IMG + blockIdx.x*16 + tx)*3;
    float bgr = bg[pi+0], bgg = bg[pi+1], bgb = bg[pi+2];

    float T = 1.0f, cr = 0.0f, cg = 0.0f, cb = 0.0f;

    #pragma unroll 1
    for (int chunk = 0; chunk < 4; chunk++) {
        int buf = chunk & 1;
        int g = chunk*256 + tid;
        float4 cu = g_cull[g];
        float cx = fminf(fmaxf(cu.x, x0), x1) - cu.x;
        float cy = fminf(fmaxf(cu.y, y0), y1) - cu.y;
        bool keep = (cx*cx + cy*cy) <= cu.z;
        unsigned bal = __ballot_sync(0xffffffffu, keep);
        if (lane == 0) sW[buf][warp] = __popc(bal);
        __syncthreads();                       // barrier 1: counts published
        int n = 0, base = 0;
        #pragma unroll
        for (int w = 0; w < 8; w++) {
            int c = sW[buf][w];
            if (w < warp) base += c;
            n += c;
        }
        if (keep) {
            int pos = base + __popc(bal & ((1u << lane) - 1u));
            float4 qv = g_q[g];
            float4 cv = g_c[g];
            sA[buf][pos] = make_float4(cu.x, cu.y, qv.x, qv.y);
            sB[buf][pos] = make_float4(qv.z, qv.w, cv.x, cv.y);
            sC[buf][pos] = cv.z;
        }
        // barrier 2: data published + block-wide early exit
        if (__syncthreads_and(T <= T_TH)) break;

        if (T > T_TH) {
            for (int i = 0; i < n; i += 4) {
                float ax[4], rr[4], gg[4], bb[4];
                #pragma unroll
                for (int u = 0; u < 4; u++) {
                    int iu = i + u;
                    bool vld = iu < n;
                    int idx = vld ? iu : 0;
                    float4 A = sA[buf][idx];
                    float4 B = sB[buf][idx];
                    float dx = px - A.x, dy = py - A.y;
                    float qd = dx*(A.z*dx + A.w*dy) + (B.x*dy*dy + B.y);
                    float av = fminf(exp2f(qd), 0.99f);
                    ax[u] = vld ? av : 0.0f;
                    rr[u] = B.z; gg[u] = B.w; bb[u] = sC[buf][idx];
                }
                float q0 = 1.0f-ax[0], q1 = 1.0f-ax[1], q2 = 1.0f-ax[2], q3 = 1.0f-ax[3];
                float p2 = q0*q1;
                float Tn = T * (p2*(q2*q3));
                if (Tn > T_TH) {
                    // fast path: all four steps provably active (T monotone)
                    float t0 = T, t1 = T*q0, t2 = T*p2, t3 = t2*q2;
                    cr = fmaf(ax[0]*t0, rr[0], cr);
                    cg = fmaf(ax[0]*t0, gg[0], cg);
                    cb = fmaf(ax[0]*t0, bb[0], cb);
                    cr = fmaf(ax[1]*t1, rr[1], cr);
                    cg = fmaf(ax[1]*t1, gg[1], cg);
                    cb = fmaf(ax[1]*t1, bb[1], cb);
                    cr = fmaf(ax[2]*t2, rr[2], cr);
                    cg = fmaf(ax[2]*t2, gg[2], cg);
                    cb = fmaf(ax[2]*t2, bb[2], cb);
                    cr = fmaf(ax[3]*t3, rr[3], cr);
                    cg = fmaf(ax[3]*t3, gg[3], cg);
                    cb = fmaf(ax[3]*t3, bb[3], cb);
                    T = Tn;
                } else {
                    // crossing group: exact masked sequential (runs at most once)
                    #pragma unroll
                    for (int u = 0; u < 4; u++) {
                        if (T > T_TH) {
                            float w = ax[u] * T;
                            cr = fmaf(w, rr[u], cr);
                            cg = fmaf(w, gg[u], cg);
                            cb = fmaf(w, bb[u], cb);
                            T *= (1.0f - ax[u]);
                        }
                    }
                }
                if (T <= T_TH) break;
            }
        }
    }

    out[pi+0] = cr + T*bgr;
    out[pi+1] = cg + T*bgg;
    out[pi+2] = cb + T*bgb;
}

extern "C" void kernel_launch(void* const* d_in, const int* in_sizes, int n_in,
                              void* d_out, int out_size) {
    const float* mean    = (const float*)d_in[0];
    const float* cov     = (const float*)d_in[1];
    const float* color   = (const float*)d_in[2];
    const float* alpha   = (const float*)d_in[3];
    const float* depth   = (const float*)d_in[4];
    const float* bg      = (const float*)d_in[5];
    const float* topleft = (const float*)d_in[6];

    prep_kernel<<<8, 128>>>(mean, cov, color, alpha, depth);
    dim3 grid(IMG/16, IMG/16), block(256);
    render_kernel<<<grid, block>>>(bg, topleft, (float*)d_out);
}

// round 6
// speedup vs baseline: 1.3380x; 1.1391x over previous
#include <cuda_runtime.h>

#define IMG 256
#define NG 1024
#define PIX (1.0f/256.0f)
#define T_TH 1e-4f

// Sorted + packed per-Gaussian data (device scratch, no allocs)
// g_cull: mx, my, rad2, pad
// g_q:    c00', c01', c11', k'   (c' = -0.5*log2e*invCov, k' = log2(alpha))
// g_c:    cr, cg, cb, pad
__device__ float4 g_cull[NG];
__device__ float4 g_q[NG];
__device__ float4 g_c[NG];

// ---------------------------------------------------------------------------
// Kernel 1: parallel rank sort (8 blocks x 128 threads), float4-vectorized
// compare loop with 4 accumulators; scatter packed records to sorted slots.
// ---------------------------------------------------------------------------
__global__ void __launch_bounds__(128) prep_kernel(const float* __restrict__ mean,
                                                   const float* __restrict__ cov,
                                                   const float* __restrict__ color,
                                                   const float* __restrict__ alpha,
                                                   const float* __restrict__ depth) {
    __shared__ float4 sd4[NG/4];
    int tid = threadIdx.x;
    const float4* d4g = (const float4*)depth;
    for (int i = tid; i < NG/4; i += 128) sd4[i] = d4g[i];
    __syncthreads();

    int i = blockIdx.x*128 + tid;
    float di = ((const float*)sd4)[i];
    int r0 = 0, r1 = 0, r2 = 0, r3 = 0;
    #pragma unroll 4
    for (int j4 = 0; j4 < NG/4; j4++) {
        float4 d = sd4[j4];
        int j = j4*4;
        r0 += (d.x < di) || (d.x == di && (j+0) < i);
        r1 += (d.y < di) || (d.y == di && (j+1) < i);
        r2 += (d.z < di) || (d.z == di && (j+2) < i);
        r3 += (d.w < di) || (d.w == di && (j+3) < i);
    }
    int rank = (r0 + r1) + (r2 + r3);

    float a = cov[i*4+0], b = cov[i*4+1], c = cov[i*4+2], d = cov[i*4+3];
    float det = a*d - b*c;
    const float L2E = 1.4426950408889634f;
    float i00  = d / det;
    float i11  = a / det;
    float ioff = -(b + c) / det;
    float mx = mean[i*2+0], my = mean[i*2+1];
    // conservative radius^2: quad > 40 outside => contribution < alpha*e^-20
    float bs      = 0.5f*(b + c);
    float half_tr = 0.5f*(a + d);
    float disc    = sqrtf(0.25f*(a - d)*(a - d) + bs*bs);
    float al = alpha[i];
    g_cull[rank] = make_float4(mx, my, 40.0f*(half_tr + disc), 0.0f);
    g_q[rank]    = make_float4(-0.5f*L2E*i00, -0.5f*L2E*ioff, -0.5f*L2E*i11,
                               __log2f(fmaxf(al, 1e-30f)));
    g_c[rank]    = make_float4(color[i*3+0], color[i*3+1], color[i*3+2], 0.0f);
}

// ---------------------------------------------------------------------------
// Kernel 2: 256 threads per 16x16 pixel tile (256 blocks).
// ONE up-front cull+compact of all 1024 sorted Gaussians into a contiguous
// depth-ordered smem list (thread t owns ranks 4t..4t+3; shfl intra-warp scan
// + one 8-entry cross-warp scan; 2 barriers total). List padded with 3
// zero-alpha dummies so the composite loop needs no validity selects and no
// barriers — just a per-pixel early break on transmittance.
// ---------------------------------------------------------------------------
__global__ void __launch_bounds__(256) render_kernel(const float* __restrict__ bg,
                                                     const float* __restrict__ topleft,
                                                     float* __restrict__ out) {
    __shared__ float4 sA[NG+4];   // mx, my, c00', c01'
    __shared__ float4 sB[NG+4];   // c11', k', cr, cg
    __shared__ float  sC[NG+4];   // cb
    __shared__ int    sW[8];      // per-warp survivor counts

    int tid  = threadIdx.x;
    int lane = tid & 31, warp = tid >> 5;

    float tlx = topleft[0], tly = topleft[1];
    float x0 = (blockIdx.x*16 + 0.5f)*PIX - tlx;
    float x1 = (blockIdx.x*16 + 15.5f)*PIX - tlx;
    float y0 = (blockIdx.y*16 + 0.5f)*PIX - tly;
    float y1 = (blockIdx.y*16 + 15.5f)*PIX - tly;

    // ---- cull 4 consecutive ranks per thread ----
    int g0 = tid*4;
    float4 cu0 = g_cull[g0+0];
    float4 cu1 = g_cull[g0+1];
    float4 cu2 = g_cull[g0+2];
    float4 cu3 = g_cull[g0+3];
    unsigned m = 0;
    {
        float cx, cy;
        cx = fminf(fmaxf(cu0.x, x0), x1) - cu0.x;
        cy = fminf(fmaxf(cu0.y, y0), y1) - cu0.y;
        if (cx*cx + cy*cy <= cu0.z) m |= 1u;
        cx = fminf(fmaxf(cu1.x, x0), x1) - cu1.x;
        cy = fminf(fmaxf(cu1.y, y0), y1) - cu1.y;
        if (cx*cx + cy*cy <= cu1.z) m |= 2u;
        cx = fminf(fmaxf(cu2.x, x0), x1) - cu2.x;
        cy = fminf(fmaxf(cu2.y, y0), y1) - cu2.y;
        if (cx*cx + cy*cy <= cu2.z) m |= 4u;
        cx = fminf(fmaxf(cu3.x, x0), x1) - cu3.x;
        cy = fminf(fmaxf(cu3.y, y0), y1) - cu3.y;
        if (cx*cx + cy*cy <= cu3.z) m |= 8u;
    }
    int cnt = __popc(m);
    // intra-warp inclusive scan of cnt
    int scan = cnt;
    #pragma unroll
    for (int d = 1; d < 32; d <<= 1) {
        int v = __shfl_up_sync(0xffffffffu, scan, d);
        if (lane >= d) scan += v;
    }
    if (lane == 31) sW[warp] = scan;        // warp total
    __syncthreads();                         // barrier 1: warp totals
    int4 w0 = *(const int4*)&sW[0];
    int4 w1 = *(const int4*)&sW[4];
    int ntot = (w0.x + w0.y + w0.z + w0.w) + (w1.x + w1.y + w1.z + w1.w);
    int base = 0;
    if (warp > 0) base += w0.x;
    if (warp > 1) base += w0.y;
    if (warp > 2) base += w0.z;
    if (warp > 3) base += w0.w;
    if (warp > 4) base += w1.x;
    if (warp > 5) base += w1.y;
    if (warp > 6) base += w1.z;
    int pos = base + (scan - cnt);
    // scatter survivors in depth order
    #pragma unroll
    for (int u = 0; u < 4; u++) {
        if (m & (1u << u)) {
            float4 cu = (u == 0) ? cu0 : (u == 1) ? cu1 : (u == 2) ? cu2 : cu3;
            float4 qv = g_q[g0+u];
            float4 cv = g_c[g0+u];
            sA[pos] = make_float4(cu.x, cu.y, qv.x, qv.y);
            sB[pos] = make_float4(qv.z, qv.w, cv.x, cv.y);
            sC[pos] = cv.z;
            pos++;
        }
    }
    if (tid == 0) {                          // zero-alpha padding (exact no-op)
        #pragma unroll
        for (int u = 0; u < 3; u++) {
            sA[ntot+u] = make_float4(0.f, 0.f, 0.f, 0.f);
            sB[ntot+u] = make_float4(0.f, -1e30f, 0.f, 0.f);
            sC[ntot+u] = 0.f;
        }
    }
    __syncthreads();                         // barrier 2: list published
    int n = (ntot + 3) & ~3;

    // ---- composite (no barriers, per-pixel early exit) ----
    int tx = tid & 15, ty = tid >> 4;
    float px = (blockIdx.x*16 + tx + 0.5f)*PIX - tlx;
    float py = (blockIdx.y*16 + ty + 0.5f)*PIX - tly;
    int pi = ((blockIdx.y*16 + ty)*IMG + blockIdx.x*16 + tx)*3;
    float bgr = bg[pi+0], bgg = bg[pi+1], bgb = bg[pi+2];

    float T = 1.0f, cr = 0.0f, cg = 0.0f, cb = 0.0f;

    for (int i = 0; i < n; i += 4) {
        float ax[4], rr[4], gg[4], bb[4];
        #pragma unroll
        for (int u = 0; u < 4; u++) {
            float4 A = sA[i+u];
            float4 B = sB[i+u];
            float dx = px - A.x, dy = py - A.y;
            float qd = dx*(A.z*dx + A.w*dy) + (B.x*dy*dy + B.y);
            ax[u] = fminf(exp2f(qd), 0.99f);
            rr[u] = B.z; gg[u] = B.w; bb[u] = sC[i+u];
        }
        float q0 = 1.0f-ax[0], q1 = 1.0f-ax[1], q2 = 1.0f-ax[2], q3 = 1.0f-ax[3];
        float p2 = q0*q1;
        float Tn = T * (p2*(q2*q3));
        if (Tn > T_TH) {
            // fast path: all four steps provably active (T monotone decreasing)
            float t0 = T, t1 = T*q0, t2 = T*p2, t3 = t2*q2;
            cr = fmaf(ax[0]*t0, rr[0], cr);
            cg = fmaf(ax[0]*t0, gg[0], cg);
            cb = fmaf(ax[0]*t0, bb[0], cb);
            cr = fmaf(ax[1]*t1, rr[1], cr);
            cg = fmaf(ax[1]*t1, gg[1], cg);
            cb = fmaf(ax[1]*t1, bb[1], cb);
            cr = fmaf(ax[2]*t2, rr[2], cr);
            cg = fmaf(ax[2]*t2, gg[2], cg);
            cb = fmaf(ax[2]*t2, bb[2], cb);
            cr = fmaf(ax[3]*t3, rr[3], cr);
            cg = fmaf(ax[3]*t3, gg[3], cg);
            cb = fmaf(ax[3]*t3, bb[3], cb);
            T = Tn;
        } else {
            // crossing group: exact masked sequential (runs at most once)
            #pragma unroll
            for (int u = 0; u < 4; u++) {
                if (T > T_TH) {
                    float w = ax[u] * T;
                    cr = fmaf(w, rr[u], cr);
                    cg = fmaf(w, gg[u], cg);
                    cb = fmaf(w, bb[u], cb);
                    T *= (1.0f - ax[u]);
                }
            }
            if (T <= T_TH) break;
        }
    }

    out[pi+0] = cr + T*bgr;
    out[pi+1] = cg + T*bgg;
    out[pi+2] = cb + T*bgb;
}

extern "C" void kernel_launch(void* const* d_in, const int* in_sizes, int n_in,
                              void* d_out, int out_size) {
    const float* mean    = (const float*)d_in[0];
    const float* cov     = (const float*)d_in[1];
    const float* color   = (const float*)d_in[2];
    const float* alpha   = (const float*)d_in[3];
    const float* depth   = (const float*)d_in[4];
    const float* bg      = (const float*)d_in[5];
    const float* topleft = (const float*)d_in[6];

    prep_kernel<<<8, 128>>>(mean, cov, color, alpha, depth);
    dim3 grid(IMG/16, IMG/16), block(256);
    render_kernel<<<grid, block>>>(bg, topleft, (float*)d_out);
}

// round 7
// speedup vs baseline: 1.7097x; 1.2778x over previous
#include <cuda_runtime.h>

#define IMG 256
#define NG 1024
#define PIX (1.0f/256.0f)
#define T_TH 1e-4f
#define QCUT 28.0f   // cull: quad > 28 => contribution < alpha*e^-14 (~8e-7)

// Sorted + packed per-Gaussian data (device scratch, no allocs)
// g_cull: mx, my, rad2, pad
// g_q:    c00', c01', c11', k'   (c' = -0.5*log2e*invCov, k' = log2(alpha))
// g_c:    cr, cg, cb, pad
__device__ float4 g_cull[NG];
__device__ float4 g_q[NG];
__device__ float4 g_c[NG];

// ---------------------------------------------------------------------------
// Kernel 1: parallel rank sort, 2 threads per Gaussian (16 blocks x 128).
// Each thread of a pair counts over half the array; combined via shfl_xor.
// Even thread precomputes the packed record and scatters to sorted slot.
// ---------------------------------------------------------------------------
__global__ void __launch_bounds__(128) prep_kernel(const float* __restrict__ mean,
                                                   const float* __restrict__ cov,
                                                   const float* __restrict__ color,
                                                   const float* __restrict__ alpha,
                                                   const float* __restrict__ depth) {
    __shared__ float4 sd4[NG/4];
    int tid = threadIdx.x;
    const float4* d4g = (const float4*)depth;
    for (int i = tid; i < NG/4; i += 128) sd4[i] = d4g[i];
    __syncthreads();

    int i    = blockIdx.x*64 + (tid >> 1);   // Gaussian id
    int half = tid & 1;                      // which half of the compare range
    float di = ((const float*)sd4)[i];
    int r0 = 0, r1 = 0, r2 = 0, r3 = 0;
    int j4beg = half * (NG/8);
    #pragma unroll 4
    for (int j4 = j4beg; j4 < j4beg + NG/8; j4++) {
        float4 d = sd4[j4];
        int j = j4*4;
        r0 += (d.x < di) || (d.x == di && (j+0) < i);
        r1 += (d.y < di) || (d.y == di && (j+1) < i);
        r2 += (d.z < di) || (d.z == di && (j+2) < i);
        r3 += (d.w < di) || (d.w == di && (j+3) < i);
    }
    int rpart = (r0 + r1) + (r2 + r3);
    int rank  = rpart + __shfl_xor_sync(0xffffffffu, rpart, 1);

    if (half == 0) {
        float a = cov[i*4+0], b = cov[i*4+1], c = cov[i*4+2], d = cov[i*4+3];
        float det = a*d - b*c;
        const float L2E = 1.4426950408889634f;
        float i00  = d / det;
        float i11  = a / det;
        float ioff = -(b + c) / det;
        float mx = mean[i*2+0], my = mean[i*2+1];
        float bs      = 0.5f*(b + c);
        float half_tr = 0.5f*(a + d);
        float disc    = sqrtf(0.25f*(a - d)*(a - d) + bs*bs);
        float al = alpha[i];
        g_cull[rank] = make_float4(mx, my, QCUT*(half_tr + disc), 0.0f);
        g_q[rank]    = make_float4(-0.5f*L2E*i00, -0.5f*L2E*ioff, -0.5f*L2E*i11,
                                   __log2f(fmaxf(al, 1e-30f)));
        g_c[rank]    = make_float4(color[i*3+0], color[i*3+1], color[i*3+2], 0.0f);
    }
}

// ---------------------------------------------------------------------------
// Kernel 2: 256 threads per 16x16 pixel tile (256 blocks).
// One up-front cull+compact of all 1024 sorted Gaussians into a contiguous
// depth-ordered smem list (2 barriers total), padded with 8 zero-alpha
// dummies. Composite: software-pipelined groups of 4 (prefetch next group's
// registers while computing), colors loaded as one float4 per group.
// ---------------------------------------------------------------------------
__global__ void __launch_bounds__(256) render_kernel(const float* __restrict__ bg,
                                                     const float* __restrict__ topleft,
                                                     float* __restrict__ out) {
    __shared__ float4 sA[NG+8];        // mx, my, c00', c01'
    __shared__ float4 sB[NG+8];        // c11', k', cr, cg
    __shared__ float4 sC4[(NG+8)/4];   // cb, packed 4 per float4
    __shared__ int    sW[8];

    int tid  = threadIdx.x;
    int lane = tid & 31, warp = tid >> 5;

    float tlx = topleft[0], tly = topleft[1];
    float x0 = (blockIdx.x*16 + 0.5f)*PIX - tlx;
    float x1 = (blockIdx.x*16 + 15.5f)*PIX - tlx;
    float y0 = (blockIdx.y*16 + 0.5f)*PIX - tly;
    float y1 = (blockIdx.y*16 + 15.5f)*PIX - tly;

    // ---- cull 4 consecutive ranks per thread ----
    int g0 = tid*4;
    float4 cu0 = g_cull[g0+0];
    float4 cu1 = g_cull[g0+1];
    float4 cu2 = g_cull[g0+2];
    float4 cu3 = g_cull[g0+3];
    unsigned m = 0;
    {
        float cx, cy;
        cx = fminf(fmaxf(cu0.x, x0), x1) - cu0.x;
        cy = fminf(fmaxf(cu0.y, y0), y1) - cu0.y;
        if (cx*cx + cy*cy <= cu0.z) m |= 1u;
        cx = fminf(fmaxf(cu1.x, x0), x1) - cu1.x;
        cy = fminf(fmaxf(cu1.y, y0), y1) - cu1.y;
        if (cx*cx + cy*cy <= cu1.z) m |= 2u;
        cx = fminf(fmaxf(cu2.x, x0), x1) - cu2.x;
        cy = fminf(fmaxf(cu2.y, y0), y1) - cu2.y;
        if (cx*cx + cy*cy <= cu2.z) m |= 4u;
        cx = fminf(fmaxf(cu3.x, x0), x1) - cu3.x;
        cy = fminf(fmaxf(cu3.y, y0), y1) - cu3.y;
        if (cx*cx + cy*cy <= cu3.z) m |= 8u;
    }
    int cnt = __popc(m);
    int scan = cnt;
    #pragma unroll
    for (int d = 1; d < 32; d <<= 1) {
        int v = __shfl_up_sync(0xffffffffu, scan, d);
        if (lane >= d) scan += v;
    }
    if (lane == 31) sW[warp] = scan;
    __syncthreads();                         // barrier 1: warp totals
    int4 w0 = *(const int4*)&sW[0];
    int4 w1 = *(const int4*)&sW[4];
    int ntot = (w0.x + w0.y + w0.z + w0.w) + (w1.x + w1.y + w1.z + w1.w);
    int base = 0;
    if (warp > 0) base += w0.x;
    if (warp > 1) base += w0.y;
    if (warp > 2) base += w0.z;
    if (warp > 3) base += w0.w;
    if (warp > 4) base += w1.x;
    if (warp > 5) base += w1.y;
    if (warp > 6) base += w1.z;
    int pos = base + (scan - cnt);
    #pragma unroll
    for (int u = 0; u < 4; u++) {
        if (m & (1u << u)) {
            float4 cu = (u == 0) ? cu0 : (u == 1) ? cu1 : (u == 2) ? cu2 : cu3;
            float4 qv = g_q[g0+u];
            float4 cv = g_c[g0+u];
            sA[pos] = make_float4(cu.x, cu.y, qv.x, qv.y);
            sB[pos] = make_float4(qv.z, qv.w, cv.x, cv.y);
            ((float*)sC4)[pos] = cv.z;
            pos++;
        }
    }
    if (tid < 8) {                           // 8 zero-alpha dummies (exact no-op)
        sA[ntot+tid] = make_float4(0.f, 0.f, 0.f, 0.f);
        sB[ntot+tid] = make_float4(0.f, -1e30f, 0.f, 0.f);
        ((float*)sC4)[ntot+tid] = 0.f;
    }
    __syncthreads();                         // barrier 2: list published
    int n = (ntot + 3) & ~3;

    // ---- composite: pipelined groups of 4, no barriers, early break ----
    int tx = tid & 15, ty = tid >> 4;
    float px = (blockIdx.x*16 + tx + 0.5f)*PIX - tlx;
    float py = (blockIdx.y*16 + ty + 0.5f)*PIX - tly;
    int pi = ((blockIdx.y*16 + ty)*IMG + blockIdx.x*16 + tx)*3;
    float bgr = bg[pi+0], bgg = bg[pi+1], bgb = bg[pi+2];

    float T = 1.0f, cr = 0.0f, cg = 0.0f, cb = 0.0f;

    float4 A0 = sA[0], A1 = sA[1], A2 = sA[2], A3 = sA[3];
    float4 B0 = sB[0], B1 = sB[1], B2 = sB[2], B3 = sB[3];
    float4 Cv = sC4[0];

    #pragma unroll 2
    for (int i = 0; i < n; i += 4) {
        // prefetch next group (always in-bounds: 8 dummies past ntot)
        float4 nA0 = sA[i+4], nA1 = sA[i+5], nA2 = sA[i+6], nA3 = sA[i+7];
        float4 nB0 = sB[i+4], nB1 = sB[i+5], nB2 = sB[i+6], nB3 = sB[i+7];
        float4 nCv = sC4[i/4 + 1];

        float ax[4];
        {
            float dx, dy, qd;
            dx = px - A0.x; dy = py - A0.y;
            qd = dx*(A0.z*dx + A0.w*dy) + (B0.x*dy*dy + B0.y);
            ax[0] = fminf(exp2f(qd), 0.99f);
            dx = px - A1.x; dy = py - A1.y;
            qd = dx*(A1.z*dx + A1.w*dy) + (B1.x*dy*dy + B1.y);
            ax[1] = fminf(exp2f(qd), 0.99f);
            dx = px - A2.x; dy = py - A2.y;
            qd = dx*(A2.z*dx + A2.w*dy) + (B2.x*dy*dy + B2.y);
            ax[2] = fminf(exp2f(qd), 0.99f);
            dx = px - A3.x; dy = py - A3.y;
            qd = dx*(A3.z*dx + A3.w*dy) + (B3.x*dy*dy + B3.y);
            ax[3] = fminf(exp2f(qd), 0.99f);
        }
        float q0 = 1.0f-ax[0], q1 = 1.0f-ax[1], q2 = 1.0f-ax[2], q3 = 1.0f-ax[3];
        float p2 = q0*q1;
        float Tn = T * (p2*(q2*q3));
        if (Tn > T_TH) {
            // fast path: all four steps provably active (T monotone decreasing)
            float t0 = T, t1 = T*q0, t2 = T*p2, t3 = t2*q2;
            float w0v = ax[0]*t0, w1v = ax[1]*t1, w2v = ax[2]*t2, w3v = ax[3]*t3;
            cr = fmaf(w0v, B0.z, cr); cg = fmaf(w0v, B0.w, cg); cb = fmaf(w0v, Cv.x, cb);
            cr = fmaf(w1v, B1.z, cr); cg = fmaf(w1v, B1.w, cg); cb = fmaf(w1v, Cv.y, cb);
            cr = fmaf(w2v, B2.z, cr); cg = fmaf(w2v, B2.w, cg); cb = fmaf(w2v, Cv.z, cb);
            cr = fmaf(w3v, B3.z, cr); cg = fmaf(w3v, B3.w, cg); cb = fmaf(w3v, Cv.w, cb);
            T = Tn;
        } else {
            // crossing group: exact masked sequential (runs at most once)
            float rr[4] = {B0.z, B1.z, B2.z, B3.z};
            float gg[4] = {B0.w, B1.w, B2.w, B3.w};
            float bb[4] = {Cv.x, Cv.y, Cv.z, Cv.w};
            #pragma unroll
            for (int u = 0; u < 4; u++) {
                if (T > T_TH) {
                    float w = ax[u] * T;
                    cr = fmaf(w, rr[u], cr);
                    cg = fmaf(w, gg[u], cg);
                    cb = fmaf(w, bb[u], cb);
                    T *= (1.0f - ax[u]);
                }
            }
            if (T <= T_TH) break;
        }
        A0 = nA0; A1 = nA1; A2 = nA2; A3 = nA3;
        B0 = nB0; B1 = nB1; B2 = nB2; B3 = nB3;
        Cv = nCv;
    }

    out[pi+0] = cr + T*bgr;
    out[pi+1] = cg + T*bgg;
    out[pi+2] = cb + T*bgb;
}

extern "C" void kernel_launch(void* const* d_in, const int* in_sizes, int n_in,
                              void* d_out, int out_size) {
    const float* mean    = (const float*)d_in[0];
    const float* cov     = (const float*)d_in[1];
    const float* color   = (const float*)d_in[2];
    const float* alpha   = (const float*)d_in[3];
    const float* depth   = (const float*)d_in[4];
    const float* bg      = (const float*)d_in[5];
    const float* topleft = (const float*)d_in[6];

    prep_kernel<<<16, 128>>>(mean, cov, color, alpha, depth);
    dim3 grid(IMG/16, IMG/16), block(256);
    render_kernel<<<grid, block>>>(bg, topleft, (float*)d_out);
}